// round 1
// baseline (speedup 1.0000x reference)
#include <cuda_runtime.h>

#define D  256
#define C  64
#define MAXNQ 4096
#define MAXNS 8192

// Scratch (device globals — no allocations allowed). All fully overwritten
// every launch; safe under graph replay.
__device__ float g_qn[MAXNQ];
__device__ float g_sn[MAXNS];
__device__ float g_cent[C * D];
__device__ float g_ssum[C];
__device__ int   g_counts[C];
__device__ int   g_start[C + 1];
__device__ int   g_cidx[MAXNS];
__device__ float g_res[MAXNQ];

__device__ __forceinline__ float warp_sum(float v) {
#pragma unroll
    for (int o = 16; o; o >>= 1) v += __shfl_xor_sync(0xffffffffu, v, o);
    return v;
}

// ---------------------------------------------------------------------------
// Kernel 1: squared row norms for xq and xs. One warp per row (64 float4/row).
// ---------------------------------------------------------------------------
__global__ void k_norms(const float* __restrict__ xq, const float* __restrict__ xs,
                        int Nq, int Ns) {
    int warp = (blockIdx.x * blockDim.x + threadIdx.x) >> 5;
    int lane = threadIdx.x & 31;
    int total = Nq + Ns;
    if (warp >= total) return;
    const float* row = (warp < Nq) ? (xq + (size_t)warp * D)
                                   : (xs + (size_t)(warp - Nq) * D);
    const float4* r4 = (const float4*)row;
    float4 a = r4[lane];
    float4 b = r4[lane + 32];
    float s = a.x*a.x + a.y*a.y + a.z*a.z + a.w*a.w
            + b.x*b.x + b.y*b.y + b.z*b.z + b.w*b.w;
    s = warp_sum(s);
    if (lane == 0) {
        if (warp < Nq) g_qn[warp] = s;
        else           g_sn[warp - Nq] = s;
    }
}

// ---------------------------------------------------------------------------
// Kernel 2: counts + class member lists (counting sort). Single CTA.
// ---------------------------------------------------------------------------
__global__ void k_classlists(const int* __restrict__ ys, int Ns) {
    __shared__ int cnt[C];
    __shared__ int off[C];
    int tid = threadIdx.x;
    if (tid < C) cnt[tid] = 0;
    __syncthreads();
    for (int j = tid; j < Ns; j += blockDim.x) atomicAdd(&cnt[ys[j]], 1);
    __syncthreads();
    if (tid == 0) {
        int acc = 0;
        for (int c = 0; c < C; c++) {
            g_counts[c] = cnt[c];
            g_start[c]  = acc;
            off[c]      = acc;
            acc += cnt[c];
        }
        g_start[C] = acc;
    }
    __syncthreads();
    for (int j = tid; j < Ns; j += blockDim.x) {
        int p = atomicAdd(&off[ys[j]], 1);
        g_cidx[p] = j;
    }
}

// ---------------------------------------------------------------------------
// Kernel 3: per-class centroids (sum of xs rows) and sum of sq-norms.
// Grid = C, 256 threads (thread d owns dim d). Coalesced row reads.
// ---------------------------------------------------------------------------
__global__ void k_cent(const float* __restrict__ xs) {
    int c = blockIdx.x, tid = threadIdx.x;
    int s0 = g_start[c], s1 = g_start[c + 1];
    float acc = 0.0f, ss = 0.0f;
    for (int m = s0; m < s1; m++) {
        int j = g_cidx[m];
        acc += xs[(size_t)j * D + tid];
        if (((m - s0) & 255) == tid) ss += g_sn[j];
    }
    g_cent[c * D + tid] = acc;
    __shared__ float sred[256];
    sred[tid] = ss;
    __syncthreads();
    for (int s = 128; s; s >>= 1) {
        if (tid < s) sred[tid] += sred[tid + s];
        __syncthreads();
    }
    if (tid == 0) g_ssum[c] = sred[0];
}

// ---------------------------------------------------------------------------
// Kernel 4: main per-query kernel. Grid = Nq, 128 threads (4 warps).
//  Phase A: 64 class dots with centroids -> summed[i,c] (closed form).
//  Phase B: in-class logits (warp-cooperative dots) -> online logsumexp.
//  Thread 0: diagonal correction, normalized logsumexp, result.
// ---------------------------------------------------------------------------
__global__ void k_main(const float* __restrict__ xq, const int* __restrict__ yq,
                       const float* __restrict__ xs, const int* __restrict__ ys,
                       const int* __restrict__ pos) {
    int i    = blockIdx.x;
    int tid  = threadIdx.x;
    int lane = tid & 31;
    int w    = tid >> 5;

    __shared__ __align__(16) float s_xq[D];
    __shared__ float s_sum[C];
    __shared__ float s_dp;
    __shared__ float s_pm[4], s_ps[4];

    // Load xq row into smem (coalesced float4).
    const float4* q4 = (const float4*)(xq + (size_t)i * D);
    if (tid < 64) ((float4*)s_xq)[tid] = q4[tid];
    __syncthreads();

    // Each lane caches its slice: dims [4*lane..4*lane+3] and [128+4*lane..].
    float4 qa = ((const float4*)s_xq)[lane];
    float4 qb = ((const float4*)s_xq)[lane + 32];

    float qn  = g_qn[i];
    int   yqi = yq[i];
    int   p   = pos[i];
    float v   = (g_counts[yqi] > 1) ? -1000.0f : 0.0f;

    // dot(xq_i, xs[p]) by warp 0 (needed for diagonal correction).
    if (w == 0) {
        const float4* r = (const float4*)(xs + (size_t)p * D);
        float4 a = r[lane], b = r[lane + 32];
        float d = qa.x*a.x + qa.y*a.y + qa.z*a.z + qa.w*a.w
                + qb.x*b.x + qb.y*b.y + qb.z*b.z + qb.w*b.w;
        d = warp_sum(d);
        if (lane == 0) s_dp = d;
    }

    // Phase A: class sums. Warp w handles classes w, w+4, ...
    for (int c = w; c < C; c += 4) {
        const float4* r = (const float4*)(g_cent + c * D);
        float4 a = r[lane], b = r[lane + 32];
        float d = qa.x*a.x + qa.y*a.y + qa.z*a.z + qa.w*a.w
                + qb.x*b.x + qb.y*b.y + qb.z*b.z + qb.w*b.w;
        d = warp_sum(d);
        if (lane == 0)
            s_sum[c] = -0.5f * ((float)g_counts[c] * qn + g_ssum[c]) + d;
    }

    // Phase B: in-class logits + online logsumexp. Warp w takes members w, w+4,...
    int s0 = g_start[yqi], s1 = g_start[yqi + 1];
    float pm = -3.0e38f, ps = 0.0f;
    for (int m = s0 + w; m < s1; m += 4) {
        int j = g_cidx[m];
        const float4* r = (const float4*)(xs + (size_t)j * D);
        float4 a = r[lane], b = r[lane + 32];
        float d = qa.x*a.x + qa.y*a.y + qa.z*a.z + qa.w*a.w
                + qb.x*b.x + qb.y*b.y + qb.z*b.z + qb.w*b.w;
        d = warp_sum(d);   // bfly: all lanes hold the full dot
        float l;
        if (j == p) {
            l = v;
        } else {
            float sq = fmaxf(qn + g_sn[j] - 2.0f * d, 0.0f);
            l = -0.5f * sq;
        }
        if (l > pm) { ps = ps * expf(pm - l) + 1.0f; pm = l; }
        else        { ps += expf(l - pm); }
    }
    if (lane == 0) { s_pm[w] = pm; s_ps[w] = ps; }
    __syncthreads();

    if (tid == 0) {
        // Diagonal override correction on summed (class of xs[pos[i]]).
        int cp = ys[p];
        float sqp   = fmaxf(qn + g_sn[p] - 2.0f * s_dp, 0.0f);
        float lorig = -0.5f * sqp;
        s_sum[cp] += v - lorig;

        // neg_logit = logsumexp_c( summed[c] / adj[c] )
        float nm = -3.0e38f;
        for (int c = 0; c < C; c++) {
            float adj = (float)g_counts[c] - (c == yqi ? 1.0f : 0.0f);
            float x = s_sum[c] / adj;
            s_sum[c] = x;
            nm = fmaxf(nm, x);
        }
        float nsum = 0.0f;
        for (int c = 0; c < C; c++) nsum += expf(s_sum[c] - nm);
        float neg = nm + logf(nsum);

        // Combine 4 warps' online logsumexp states.
        float m2 = fmaxf(fmaxf(s_pm[0], s_pm[1]), fmaxf(s_pm[2], s_pm[3]));
        float s2 = 0.0f;
        for (int k = 0; k < 4; k++) s2 += s_ps[k] * expf(s_pm[k] - m2);
        float posl = m2 + logf(s2);

        g_res[i] = neg - posl;
    }
}

// ---------------------------------------------------------------------------
// Kernel 5: mean over queries.
// ---------------------------------------------------------------------------
__global__ void k_reduce(float* __restrict__ out, int Nq) {
    __shared__ float sred[256];
    int tid = threadIdx.x;
    float a = 0.0f;
    for (int i = tid; i < Nq; i += 256) a += g_res[i];
    sred[tid] = a;
    __syncthreads();
    for (int s = 128; s; s >>= 1) {
        if (tid < s) sred[tid] += sred[tid + s];
        __syncthreads();
    }
    if (tid == 0) out[0] = sred[0] / (float)Nq;
}

extern "C" void kernel_launch(void* const* d_in, const int* in_sizes, int n_in,
                              void* d_out, int out_size) {
    const float* xq  = (const float*)d_in[0];
    const int*   yq  = (const int*)  d_in[1];
    const float* xs  = (const float*)d_in[2];
    const int*   ys  = (const int*)  d_in[3];
    const int*   pos = (const int*)  d_in[4];
    int Nq = in_sizes[1];
    int Ns = in_sizes[3];

    int rows    = Nq + Ns;
    int nthread = rows * 32;
    k_norms<<<(nthread + 255) / 256, 256>>>(xq, xs, Nq, Ns);
    k_classlists<<<1, 256>>>(ys, Ns);
    k_cent<<<C, 256>>>(xs);
    k_main<<<Nq, 128>>>(xq, yq, xs, ys, pos);
    k_reduce<<<1, 256>>>((float*)d_out, Nq);
}

// round 2
// speedup vs baseline: 1.4458x; 1.4458x over previous
#include <cuda_runtime.h>
#include <math.h>

#define D4    64            // 256 dims = 64 float4
#define C     64
#define MAXNQ 4096
#define MAXNS 8192
#define QT    32            // queries per tile
#define MB    64            // members per staged chunk
#define MAXTILES (MAXNQ/QT + C)   // 192 upper bound on sum ceil(Qc/QT)
#define NEG  (-3.0e38f)
#define SQ_STRIDE 66        // float4 stride for s_q rows (conflict-free)
#define SMEM_MAIN ((QT*SQ_STRIDE + MB*D4) * 16)   // 99328 B

// Scratch (device globals; fully rewritten every call -> replay-safe).
__device__ float g_qn[MAXNQ];
__device__ float g_sn[MAXNS];
__device__ float g_cent[C * 256];
__device__ float g_ssum[C];
__device__ int   g_counts[C];
__device__ int   g_start[C + 1];
__device__ int   g_cidx[MAXNS];
__device__ int   g_qidx[MAXNQ];
__device__ int   g_tc[MAXTILES], g_toff[MAXTILES], g_tcnt[MAXTILES];
__device__ int   g_ntiles;
__device__ float g_res[MAXNQ];

__device__ __forceinline__ float warp_sum(float v) {
#pragma unroll
    for (int o = 16; o; o >>= 1) v += __shfl_xor_sync(0xffffffffu, v, o);
    return v;
}

// ---------------------------------------------------------------------------
// Kernel 1: squared row norms (one warp per row).
// ---------------------------------------------------------------------------
__global__ void k_norms(const float* __restrict__ xq, const float* __restrict__ xs,
                        int Nq, int Ns) {
    int warp = (blockIdx.x * blockDim.x + threadIdx.x) >> 5;
    int lane = threadIdx.x & 31;
    if (warp >= Nq + Ns) return;
    const float4* r4 = (const float4*)((warp < Nq) ? (xq + (size_t)warp * 256)
                                                   : (xs + (size_t)(warp - Nq) * 256));
    float4 a = r4[lane], b = r4[lane + 32];
    float s = a.x*a.x + a.y*a.y + a.z*a.z + a.w*a.w
            + b.x*b.x + b.y*b.y + b.z*b.z + b.w*b.w;
    s = warp_sum(s);
    if (lane == 0) { if (warp < Nq) g_qn[warp] = s; else g_sn[warp - Nq] = s; }
}

// ---------------------------------------------------------------------------
// Kernel 2: class lists for support AND queries + tile schedule. Single CTA.
// ---------------------------------------------------------------------------
__global__ void k_classlists(const int* __restrict__ ys, const int* __restrict__ yq,
                             int Ns, int Nq) {
    __shared__ int cnt[C], off[C], qcnt[C], qoff[C];
    int tid = threadIdx.x;
    if (tid < C) { cnt[tid] = 0; qcnt[tid] = 0; }
    __syncthreads();
    for (int j = tid; j < Ns; j += blockDim.x) atomicAdd(&cnt[ys[j]], 1);
    for (int i = tid; i < Nq; i += blockDim.x) atomicAdd(&qcnt[yq[i]], 1);
    __syncthreads();
    if (tid == 0) {
        int acc = 0, qacc = 0, nt = 0;
        for (int c = 0; c < C; c++) {
            g_counts[c] = cnt[c]; g_start[c] = acc; off[c] = acc; acc += cnt[c];
            qoff[c] = qacc;
            for (int t = 0; t < qcnt[c]; t += QT) {
                g_tc[nt] = c; g_toff[nt] = qacc + t;
                g_tcnt[nt] = min(QT, qcnt[c] - t); nt++;
            }
            qacc += qcnt[c];
        }
        g_start[C] = acc; g_ntiles = nt;
    }
    __syncthreads();
    for (int j = tid; j < Ns; j += blockDim.x) { int p = atomicAdd(&off[ys[j]], 1);  g_cidx[p] = j; }
    for (int i = tid; i < Nq; i += blockDim.x) { int p = atomicAdd(&qoff[yq[i]], 1); g_qidx[p] = i; }
}

// ---------------------------------------------------------------------------
// Kernel 3: per-class centroids + sum of member sq-norms. Grid = C.
// ---------------------------------------------------------------------------
__global__ void k_cent(const float* __restrict__ xs) {
    int c = blockIdx.x, tid = threadIdx.x;
    int s0 = g_start[c], s1 = g_start[c + 1];
    float acc = 0.0f, ss = 0.0f;
    for (int m = s0; m < s1; m++) {
        int j = g_cidx[m];
        acc += xs[(size_t)j * 256 + tid];
        if (((m - s0) & 255) == tid) ss += g_sn[j];
    }
    g_cent[c * 256 + tid] = acc;
    __shared__ float sred[256];
    sred[tid] = ss; __syncthreads();
    for (int s = 128; s; s >>= 1) { if (tid < s) sred[tid] += sred[tid + s]; __syncthreads(); }
    if (tid == 0) g_ssum[c] = sred[0];
}

// ---------------------------------------------------------------------------
// Kernel 4: class-tiled main kernel. 256 thr = 8 warps; warp w owns queries
// 4w..4w+3; thread owns members 2l,2l+1. Register-blocked 4x2 smem GEMM.
// ---------------------------------------------------------------------------
__global__ void __launch_bounds__(256, 2)
k_main(const float* __restrict__ xq, const float* __restrict__ xs,
       const int* __restrict__ pos) {
    int b = blockIdx.x;
    if (b >= g_ntiles) return;

    extern __shared__ float4 dsm[];
    float4* s_q4 = dsm;                  // QT rows, stride SQ_STRIDE float4
    float4* s_m4 = dsm + QT * SQ_STRIDE; // MB rows, stride D4, XOR-swizzled cols
    __shared__ float s_lorig[QT];
    __shared__ float s_msn[MB];
    __shared__ int   s_mj[MB];

    int t = threadIdx.x, w = t >> 5, l = t & 31;
    int c    = g_tc[b];
    int qoff = g_toff[b];
    int qcnt = g_tcnt[b];
    float v  = (g_counts[c] > 1) ? -1000.0f : 0.0f;

    // Load 32 query rows + per-query metadata.
    float qn[4]; int p[4];
#pragma unroll
    for (int k = 0; k < 4; k++) {
        int ql = 4 * w + k;
        int qi = g_qidx[qoff + min(ql, qcnt - 1)];
        const float4* src = (const float4*)xq + (size_t)qi * D4;
        s_q4[ql * SQ_STRIDE + l]      = src[l];
        s_q4[ql * SQ_STRIDE + l + 32] = src[l + 32];
        qn[k] = g_qn[qi];
        p[k]  = pos[qi];
    }

    int s0 = g_start[c];
    int Mc = g_start[c + 1] - s0;

    float pm[4], ps[4];
#pragma unroll
    for (int k = 0; k < 4; k++) { pm[k] = NEG; ps[k] = 0.0f; }

    const int m0 = 2 * l, m1 = 2 * l + 1;
    const int sig = l & 7;                // = ((2l)>>1)&7 = ((2l+1)>>1)&7

    // ---- member chunks: positive (in-class) logsumexp ----
    for (int base = 0; base < Mc; base += MB) {
        int nm = min(MB, Mc - base);
        __syncthreads();
        for (int r = 0; r < 8; r++) {
            int m = (r << 3) + w;
            if (m < nm) {
                int j = g_cidx[s0 + base + m];
                int sg = (m >> 1) & 7;
                const float4* src = (const float4*)xs + (size_t)j * D4;
                s_m4[m * D4 + (l ^ sg)]        = src[l];
                s_m4[m * D4 + ((l + 32) ^ sg)] = src[l + 32];
                if (l == 0) { s_mj[m] = j; s_msn[m] = g_sn[j]; }
            } else if (l == 0) s_mj[m] = -1;
        }
        __syncthreads();

        float a0[4] = {0,0,0,0}, a1[4] = {0,0,0,0};
        const float4* mr0 = s_m4 + m0 * D4;
        const float4* mr1 = s_m4 + m1 * D4;
#pragma unroll 4
        for (int d = 0; d < D4; d++) {
            int cc = d ^ sig;
            float4 ma = mr0[cc];
            float4 mb = mr1[cc];
#pragma unroll
            for (int k = 0; k < 4; k++) {
                float4 q = s_q4[(4 * w + k) * SQ_STRIDE + d];
                a0[k] += q.x*ma.x + q.y*ma.y + q.z*ma.z + q.w*ma.w;
                a1[k] += q.x*mb.x + q.y*mb.y + q.z*mb.z + q.w*mb.w;
            }
        }

        int   j0 = s_mj[m0],  j1 = s_mj[m1];
        float sn0 = s_msn[m0], sn1 = s_msn[m1];
#pragma unroll
        for (int k = 0; k < 4; k++) {
            float r0 = -0.5f * fmaxf(qn[k] + sn0 - 2.0f * a0[k], 0.0f);
            float r1 = -0.5f * fmaxf(qn[k] + sn1 - 2.0f * a1[k], 0.0f);
            float l0 = (j0 < 0) ? NEG : ((j0 == p[k]) ? v : r0);
            float l1 = (j1 < 0) ? NEG : ((j1 == p[k]) ? v : r1);
            if (j0 >= 0 && j0 == p[k]) s_lorig[4 * w + k] = r0;
            if (j1 >= 0 && j1 == p[k]) s_lorig[4 * w + k] = r1;
            float mx = fmaxf(pm[k], fmaxf(l0, l1));
            if (mx > -1e37f) {
                ps[k] = ps[k] * expf(pm[k] - mx) + expf(l0 - mx) + expf(l1 - mx);
                pm[k] = mx;
            }
        }
    }

    // warp-reduce positive logsumexp (once, after all chunks)
    float posl[4];
#pragma unroll
    for (int k = 0; k < 4; k++) {
        float m = pm[k], s = ps[k];
        for (int o = 16; o; o >>= 1) {
            float om = __shfl_xor_sync(0xffffffffu, m, o);
            float os = __shfl_xor_sync(0xffffffffu, s, o);
            float mx = fmaxf(m, om);
            if (mx > -1e37f) s = s * expf(m - mx) + os * expf(om - mx);
            m = mx;
        }
        posl[k] = m + logf(s);
    }

    // ---- centroid chunk: negative term (closed form + diagonal correction) ----
    __syncthreads();
    for (int r = 0; r < 8; r++) {
        int m = (r << 3) + w;
        int sg = (m >> 1) & 7;
        const float4* src = (const float4*)g_cent + (size_t)m * D4;
        s_m4[m * D4 + (l ^ sg)]        = src[l];
        s_m4[m * D4 + ((l + 32) ^ sg)] = src[l + 32];
    }
    __syncthreads();

    {
        float b0[4] = {0,0,0,0}, b1[4] = {0,0,0,0};
        const float4* mr0 = s_m4 + m0 * D4;
        const float4* mr1 = s_m4 + m1 * D4;
#pragma unroll 4
        for (int d = 0; d < D4; d++) {
            int cc = d ^ sig;
            float4 ma = mr0[cc];
            float4 mb = mr1[cc];
#pragma unroll
            for (int k = 0; k < 4; k++) {
                float4 q = s_q4[(4 * w + k) * SQ_STRIDE + d];
                b0[k] += q.x*ma.x + q.y*ma.y + q.z*ma.z + q.w*ma.w;
                b1[k] += q.x*mb.x + q.y*mb.y + q.z*mb.z + q.w*mb.w;
            }
        }

        float cnt0 = (float)g_counts[m0], cnt1 = (float)g_counts[m1];
        float ss0 = g_ssum[m0], ss1 = g_ssum[m1];
        bool  isc0 = (m0 == c), isc1 = (m1 == c);
#pragma unroll
        for (int k = 0; k < 4; k++) {
            float lo = s_lorig[4 * w + k];
            float x0 = -0.5f * (cnt0 * qn[k] + ss0) + b0[k];
            float x1 = -0.5f * (cnt1 * qn[k] + ss1) + b1[k];
            if (isc0) x0 += v - lo;
            if (isc1) x1 += v - lo;
            x0 /= cnt0 - (isc0 ? 1.0f : 0.0f);
            x1 /= cnt1 - (isc1 ? 1.0f : 0.0f);
            float m = fmaxf(x0, x1);
            float s = expf(x0 - m) + expf(x1 - m);
            for (int o = 16; o; o >>= 1) {
                float om = __shfl_xor_sync(0xffffffffu, m, o);
                float os = __shfl_xor_sync(0xffffffffu, s, o);
                float mx = fmaxf(m, om);
                s = s * expf(m - mx) + os * expf(om - mx);
                m = mx;
            }
            if (l == 0 && 4 * w + k < qcnt) {
                float neg = m + logf(s);
                g_res[g_qidx[qoff + 4 * w + k]] = neg - posl[k];
            }
        }
    }
}

// ---------------------------------------------------------------------------
// Kernel 5: mean over queries.
// ---------------------------------------------------------------------------
__global__ void k_reduce(float* __restrict__ out, int Nq) {
    __shared__ float sred[256];
    int tid = threadIdx.x;
    float a = 0.0f;
    for (int i = tid; i < Nq; i += 256) a += g_res[i];
    sred[tid] = a; __syncthreads();
    for (int s = 128; s; s >>= 1) { if (tid < s) sred[tid] += sred[tid + s]; __syncthreads(); }
    if (tid == 0) out[0] = sred[0] / (float)Nq;
}

extern "C" void kernel_launch(void* const* d_in, const int* in_sizes, int n_in,
                              void* d_out, int out_size) {
    const float* xq  = (const float*)d_in[0];
    const int*   yq  = (const int*)  d_in[1];
    const float* xs  = (const float*)d_in[2];
    const int*   ys  = (const int*)  d_in[3];
    const int*   pos = (const int*)  d_in[4];
    int Nq = in_sizes[1];
    int Ns = in_sizes[3];

    cudaFuncSetAttribute(k_main, cudaFuncAttributeMaxDynamicSharedMemorySize, SMEM_MAIN);

    int nthread = (Nq + Ns) * 32;
    k_norms<<<(nthread + 255) / 256, 256>>>(xq, xs, Nq, Ns);
    k_classlists<<<1, 256>>>(ys, yq, Ns, Nq);
    k_cent<<<C, 256>>>(xs);
    k_main<<<MAXTILES, 256, SMEM_MAIN>>>(xq, xs, pos);
    k_reduce<<<1, 256>>>((float*)d_out, Nq);
}

// round 3
// speedup vs baseline: 1.7818x; 1.2325x over previous
#include <cuda_runtime.h>
#include <math.h>

#define D4    64            // 256 dims = 64 float4
#define C     64
#define MAXNQ 4096
#define MAXNS 8192
#define QT    16            // queries per tile
#define MB    64            // members per staged chunk
#define MAXTILES (MAXNQ/QT + C)   // 320
#define NEG  (-3.0e38f)
#define SMEM_MAIN ((QT*D4 + MB*D4) * 16)   // 80 KB dynamic

// Scratch (device globals; fully rewritten every call -> replay-safe).
__device__ float g_sn[MAXNS];
__device__ float g_cent[C * 256];
__device__ float g_ssum[C];
__device__ int   g_counts[C];
__device__ int   g_start[C + 1];
__device__ int   g_cidx[MAXNS];
__device__ int   g_qidx[MAXNQ];
__device__ int   g_tc[MAXTILES], g_toff[MAXTILES], g_tcnt[MAXTILES];
__device__ int   g_ntiles;
__device__ float g_res[MAXNQ];

__device__ __forceinline__ float warp_sum(float v) {
#pragma unroll
    for (int o = 16; o; o >>= 1) v += __shfl_xor_sync(0xffffffffu, v, o);
    return v;
}

// ---------------------------------------------------------------------------
// Kernel 1: squared row norms for xs only (one warp per row).
// ---------------------------------------------------------------------------
__global__ void k_norms(const float* __restrict__ xs, int Ns) {
    int warp = (blockIdx.x * blockDim.x + threadIdx.x) >> 5;
    int lane = threadIdx.x & 31;
    if (warp >= Ns) return;
    const float4* r4 = (const float4*)(xs + (size_t)warp * 256);
    float4 a = r4[lane], b = r4[lane + 32];
    float s = a.x*a.x + a.y*a.y + a.z*a.z + a.w*a.w
            + b.x*b.x + b.y*b.y + b.z*b.z + b.w*b.w;
    s = warp_sum(s);
    if (lane == 0) g_sn[warp] = s;
}

// ---------------------------------------------------------------------------
// Kernel 2: class lists (support + queries) + tile schedule. One wide CTA.
// ---------------------------------------------------------------------------
__global__ void k_classlists(const int* __restrict__ ys, const int* __restrict__ yq,
                             int Ns, int Nq) {
    __shared__ int cnt[C], off[C], qcnt[C], qoff[C];
    int tid = threadIdx.x;
    if (tid < C) { cnt[tid] = 0; qcnt[tid] = 0; }
    __syncthreads();
    for (int j = tid; j < Ns; j += blockDim.x) atomicAdd(&cnt[ys[j]], 1);
    for (int i = tid; i < Nq; i += blockDim.x) atomicAdd(&qcnt[yq[i]], 1);
    __syncthreads();
    if (tid == 0) {
        int acc = 0, qacc = 0, nt = 0;
        for (int c = 0; c < C; c++) {
            g_counts[c] = cnt[c]; g_start[c] = acc; off[c] = acc; acc += cnt[c];
            qoff[c] = qacc;
            for (int t = 0; t < qcnt[c]; t += QT) {
                g_tc[nt] = c; g_toff[nt] = qacc + t;
                g_tcnt[nt] = min(QT, qcnt[c] - t); nt++;
            }
            qacc += qcnt[c];
        }
        g_start[C] = acc; g_ntiles = nt;
    }
    __syncthreads();
    for (int j = tid; j < Ns; j += blockDim.x) { int p = atomicAdd(&off[ys[j]], 1);  g_cidx[p] = j; }
    for (int i = tid; i < Nq; i += blockDim.x) { int p = atomicAdd(&qoff[yq[i]], 1); g_qidx[p] = i; }
}

// ---------------------------------------------------------------------------
// Kernel 3: per-class centroids + sum of member sq-norms.
// Grid (C, 2): block y owns 128 dims. 4-way row unroll for MLP.
// ---------------------------------------------------------------------------
__global__ void k_cent(const float* __restrict__ xs) {
    int c = blockIdx.x, tid = threadIdx.x;
    int dim = blockIdx.y * 128 + tid;
    int s0 = g_start[c], s1 = g_start[c + 1];
    float acc = 0.0f;
    int m = s0;
    for (; m + 3 < s1; m += 4) {
        int j0 = g_cidx[m], j1 = g_cidx[m+1], j2 = g_cidx[m+2], j3 = g_cidx[m+3];
        float v0 = xs[(size_t)j0 * 256 + dim];
        float v1 = xs[(size_t)j1 * 256 + dim];
        float v2 = xs[(size_t)j2 * 256 + dim];
        float v3 = xs[(size_t)j3 * 256 + dim];
        acc += (v0 + v1) + (v2 + v3);
    }
    for (; m < s1; m++) acc += xs[(size_t)g_cidx[m] * 256 + dim];
    g_cent[c * 256 + dim] = acc;

    if (blockIdx.y == 0) {
        float ss = 0.0f;
        for (int k = s0 + tid; k < s1; k += 128) ss += g_sn[g_cidx[k]];
        __shared__ float sred[128];
        sred[tid] = ss; __syncthreads();
        for (int s = 64; s; s >>= 1) { if (tid < s) sred[tid] += sred[tid + s]; __syncthreads(); }
        if (tid == 0) g_ssum[c] = sred[0];
    }
}

// ---------------------------------------------------------------------------
// Kernel 4: class-tiled main kernel. 256 thr = 8 warps.
// Warp w owns queries 2w,2w+1; lane owns members 2l,2l+1. 2x2 register tile.
// 80 KB smem -> 2 CTAs/SM.
// ---------------------------------------------------------------------------
__global__ void __launch_bounds__(256, 2)
k_main(const float* __restrict__ xq, const float* __restrict__ xs,
       const int* __restrict__ pos) {
    int b = blockIdx.x;
    if (b >= g_ntiles) return;

    extern __shared__ float4 dsm[];
    float4* s_q4 = dsm;                  // QT rows x 64 float4
    float4* s_m4 = dsm + QT * D4;        // MB rows x 64 float4, XOR-swizzled
    __shared__ float s_lorig[QT];
    __shared__ float s_msn[MB];
    __shared__ int   s_mj[MB];

    int t = threadIdx.x, w = t >> 5, l = t & 31;
    int c    = g_tc[b];
    int qoff = g_toff[b];
    int qcnt = g_tcnt[b];
    float v  = (g_counts[c] > 1) ? -1000.0f : 0.0f;

    // Load 16 query rows (2 per warp) + compute q-norm in-warp + metadata.
    float qn[2]; int p[2];
#pragma unroll
    for (int k = 0; k < 2; k++) {
        int ql = 2 * w + k;
        int qi = g_qidx[qoff + min(ql, qcnt - 1)];
        const float4* src = (const float4*)xq + (size_t)qi * D4;
        float4 a = src[l], bb = src[l + 32];
        s_q4[ql * D4 + l]      = a;
        s_q4[ql * D4 + l + 32] = bb;
        float s = a.x*a.x + a.y*a.y + a.z*a.z + a.w*a.w
                + bb.x*bb.x + bb.y*bb.y + bb.z*bb.z + bb.w*bb.w;
        qn[k] = warp_sum(s);
        p[k]  = pos[qi];
    }

    int s0 = g_start[c];
    int Mc = g_start[c + 1] - s0;

    float pm[2], ps[2];
#pragma unroll
    for (int k = 0; k < 2; k++) { pm[k] = NEG; ps[k] = 0.0f; }

    const int m0 = 2 * l, m1 = 2 * l + 1;
    const int sig = l & 7;
    const float4* mr0 = s_m4 + m0 * D4;
    const float4* mr1 = s_m4 + m1 * D4;
    const float4* qr0 = s_q4 + (2 * w) * D4;
    const float4* qr1 = qr0 + D4;

    // ---- member chunks: positive (in-class) logsumexp ----
    for (int base = 0; base < Mc; base += MB) {
        int nm = min(MB, Mc - base);
        __syncthreads();
        for (int r = 0; r < 8; r++) {
            int m = (r << 3) + w;
            if (m < nm) {
                int j = g_cidx[s0 + base + m];
                int sg = (m >> 1) & 7;
                const float4* src = (const float4*)xs + (size_t)j * D4;
                s_m4[m * D4 + (l ^ sg)]        = src[l];
                s_m4[m * D4 + ((l + 32) ^ sg)] = src[l + 32];
                if (l == 0) { s_mj[m] = j; s_msn[m] = g_sn[j]; }
            } else if (l == 0) s_mj[m] = -1;
        }
        __syncthreads();

        float a00 = 0, a01 = 0, a10 = 0, a11 = 0;
#pragma unroll 4
        for (int d = 0; d < D4; d++) {
            int cc = d ^ sig;
            float4 ma = mr0[cc];
            float4 mb = mr1[cc];
            float4 q0 = qr0[d];
            float4 q1 = qr1[d];
            a00 += q0.x*ma.x + q0.y*ma.y + q0.z*ma.z + q0.w*ma.w;
            a01 += q0.x*mb.x + q0.y*mb.y + q0.z*mb.z + q0.w*mb.w;
            a10 += q1.x*ma.x + q1.y*ma.y + q1.z*ma.z + q1.w*ma.w;
            a11 += q1.x*mb.x + q1.y*mb.y + q1.z*mb.z + q1.w*mb.w;
        }

        int   j0 = s_mj[m0],  j1 = s_mj[m1];
        float sn0 = s_msn[m0], sn1 = s_msn[m1];
        float d0[2] = {a00, a10}, d1[2] = {a01, a11};
#pragma unroll
        for (int k = 0; k < 2; k++) {
            float r0 = -0.5f * fmaxf(qn[k] + sn0 - 2.0f * d0[k], 0.0f);
            float r1 = -0.5f * fmaxf(qn[k] + sn1 - 2.0f * d1[k], 0.0f);
            float l0 = (j0 < 0) ? NEG : ((j0 == p[k]) ? v : r0);
            float l1 = (j1 < 0) ? NEG : ((j1 == p[k]) ? v : r1);
            if (j0 >= 0 && j0 == p[k]) s_lorig[2 * w + k] = r0;
            if (j1 >= 0 && j1 == p[k]) s_lorig[2 * w + k] = r1;
            float mx = fmaxf(pm[k], fmaxf(l0, l1));
            if (mx > -1e37f) {
                ps[k] = ps[k] * expf(pm[k] - mx) + expf(l0 - mx) + expf(l1 - mx);
                pm[k] = mx;
            }
        }
    }

    // warp-reduce positive logsumexp
    float posl[2];
#pragma unroll
    for (int k = 0; k < 2; k++) {
        float m = pm[k], s = ps[k];
        for (int o = 16; o; o >>= 1) {
            float om = __shfl_xor_sync(0xffffffffu, m, o);
            float os = __shfl_xor_sync(0xffffffffu, s, o);
            float mx = fmaxf(m, om);
            if (mx > -1e37f) s = s * expf(m - mx) + os * expf(om - mx);
            m = mx;
        }
        posl[k] = m + logf(s);
    }

    // ---- centroid chunk: negative term (closed form + diagonal correction) ----
    __syncthreads();
    for (int r = 0; r < 8; r++) {
        int m = (r << 3) + w;
        int sg = (m >> 1) & 7;
        const float4* src = (const float4*)g_cent + (size_t)m * D4;
        s_m4[m * D4 + (l ^ sg)]        = src[l];
        s_m4[m * D4 + ((l + 32) ^ sg)] = src[l + 32];
    }
    __syncthreads();

    {
        float b00 = 0, b01 = 0, b10 = 0, b11 = 0;
#pragma unroll 4
        for (int d = 0; d < D4; d++) {
            int cc = d ^ sig;
            float4 ma = mr0[cc];
            float4 mb = mr1[cc];
            float4 q0 = qr0[d];
            float4 q1 = qr1[d];
            b00 += q0.x*ma.x + q0.y*ma.y + q0.z*ma.z + q0.w*ma.w;
            b01 += q0.x*mb.x + q0.y*mb.y + q0.z*mb.z + q0.w*mb.w;
            b10 += q1.x*ma.x + q1.y*ma.y + q1.z*ma.z + q1.w*ma.w;
            b11 += q1.x*mb.x + q1.y*mb.y + q1.z*mb.z + q1.w*mb.w;
        }

        float cnt0 = (float)g_counts[m0], cnt1 = (float)g_counts[m1];
        float ss0 = g_ssum[m0], ss1 = g_ssum[m1];
        bool  isc0 = (m0 == c), isc1 = (m1 == c);
        float e0[2] = {b00, b10}, e1[2] = {b01, b11};
#pragma unroll
        for (int k = 0; k < 2; k++) {
            float lo = s_lorig[2 * w + k];
            float x0 = -0.5f * (cnt0 * qn[k] + ss0) + e0[k];
            float x1 = -0.5f * (cnt1 * qn[k] + ss1) + e1[k];
            if (isc0) x0 += v - lo;
            if (isc1) x1 += v - lo;
            x0 /= cnt0 - (isc0 ? 1.0f : 0.0f);
            x1 /= cnt1 - (isc1 ? 1.0f : 0.0f);
            float m = fmaxf(x0, x1);
            float s = expf(x0 - m) + expf(x1 - m);
            for (int o = 16; o; o >>= 1) {
                float om = __shfl_xor_sync(0xffffffffu, m, o);
                float os = __shfl_xor_sync(0xffffffffu, s, o);
                float mx = fmaxf(m, om);
                s = s * expf(m - mx) + os * expf(om - mx);
                m = mx;
            }
            if (l == 0 && 2 * w + k < qcnt) {
                float neg = m + logf(s);
                g_res[g_qidx[qoff + 2 * w + k]] = neg - posl[k];
            }
        }
    }
}

// ---------------------------------------------------------------------------
// Kernel 5: mean over queries.
// ---------------------------------------------------------------------------
__global__ void k_reduce(float* __restrict__ out, int Nq) {
    __shared__ float sred[256];
    int tid = threadIdx.x;
    float a = 0.0f;
    for (int i = tid; i < Nq; i += 256) a += g_res[i];
    sred[tid] = a; __syncthreads();
    for (int s = 128; s; s >>= 1) { if (tid < s) sred[tid] += sred[tid + s]; __syncthreads(); }
    if (tid == 0) out[0] = sred[0] / (float)Nq;
}

extern "C" void kernel_launch(void* const* d_in, const int* in_sizes, int n_in,
                              void* d_out, int out_size) {
    const float* xq  = (const float*)d_in[0];
    const int*   yq  = (const int*)  d_in[1];
    const float* xs  = (const float*)d_in[2];
    const int*   ys  = (const int*)  d_in[3];
    const int*   pos = (const int*)  d_in[4];
    int Nq = in_sizes[1];
    int Ns = in_sizes[3];

    cudaFuncSetAttribute(k_main, cudaFuncAttributeMaxDynamicSharedMemorySize, SMEM_MAIN);

    k_norms<<<(Ns * 32 + 255) / 256, 256>>>(xs, Ns);
    k_classlists<<<1, 1024>>>(ys, yq, Ns, Nq);
    dim3 gc(C, 2);
    k_cent<<<gc, 128>>>(xs);
    k_main<<<MAXTILES, 256, SMEM_MAIN>>>(xq, xs, pos);
    k_reduce<<<1, 256>>>((float*)d_out, Nq);
}